// round 2
// baseline (speedup 1.0000x reference)
#include <cuda_runtime.h>
#include <cstddef>

// ---------------------------------------------------------------------------
// TicRows: out[n, r*256+c] = sum_e sum_i x[n, cell[r][e]*64 + i] * v[e,i,r,c]
//                            + b[r*256+c]
// mats is one-hot over board cells per (e, r)  ->  gather instead of dense GEMM.
// 49 small GEMMs: (8192 x 192) @ (192 x 256), fp32, FFMA2 (f32x2) inner loop.
// ---------------------------------------------------------------------------

#define BATCH   8192
#define ROWS    49
#define CH      256
#define KDIM    192          // 3 * 64
#define XCOLS   1728         // 27 * 64
#define OUTCOLS 12544        // 49 * 256

#define BM  128
#define BN  128
#define KC  16
#define NKC 12               // 192 / 16
#define XS  132              // sX row stride (BM + 4 pad)

__device__ int d_cell[ROWS * 3];

// Build cell[r][e]: faithful port of init_wincon_matrix(). Each column gets
// exactly 3 puts, so step is always 0,1,2 within a column.
__global__ void init_cells_kernel() {
    if (threadIdx.x != 0) return;
    int step = 0, col = 0;
    auto put = [&](int x, int y, int z) {
        d_cell[col * 3 + step] = x + 3 * y + 9 * z;
        step = (step + 1) % 3;
    };
    for (int x = 0; x < 3; x++) {
        for (int y = 0; y < 3; y++) { for (int z = 0; z < 3; z++) put(x, y, z); col++; }
        for (int z = 0; z < 3; z++) { for (int y = 0; y < 3; y++) put(x, y, z); col++; }
        for (int y = 0; y < 3; y++) put(x, y, y);       col++;
        for (int y = 0; y < 3; y++) put(x, y, 2 - y);   col++;
    }
    for (int z = 0; z < 3; z++) {
        for (int y = 0; y < 3; y++) { for (int x = 0; x < 3; x++) put(x, y, z); col++; }
        for (int y = 0; y < 3; y++) put(y, y, z);       col++;
        for (int y = 0; y < 3; y++) put(2 - y, y, z);   col++;
    }
    for (int y = 0; y < 3; y++) {
        for (int z = 0; z < 3; z++) put(z, y, z);       col++;
        for (int z = 0; z < 3; z++) put(2 - z, y, z);   col++;
    }
    for (int x = 0; x < 3; x++) put(x, x, x);           col++;
    for (int x = 0; x < 3; x++) put(x, 2 - x, 2 - x);   col++;
    for (int x = 0; x < 3; x++) put(x, x, 2 - x);       col++;
    for (int x = 0; x < 3; x++) put(x, 2 - x, x);       col++;
}

// Packed dual-FMA: d.xy += a.xy * b.xy   (Blackwell full-rate fp32 path)
__device__ __forceinline__ void ffma2(float2& d, float2 a, float2 b) {
    asm("fma.rn.f32x2 %0, %1, %2, %0;"
        : "+l"(*reinterpret_cast<unsigned long long*>(&d))
        : "l"(*reinterpret_cast<const unsigned long long*>(&a)),
          "l"(*reinterpret_cast<const unsigned long long*>(&b)));
}

__global__ __launch_bounds__(256, 2)
void ticrows_kernel(const float* __restrict__ x,
                    const float* __restrict__ v,
                    const float* __restrict__ bias,
                    float* __restrict__ out) {
    __shared__ float sX[2][KC * XS];   // transposed: sX[k][m]
    __shared__ float sV[2][KC * BN];   // sV[k][c]

    const int tid   = threadIdx.x;
    const int m0    = blockIdx.x * BM;
    const int r     = blockIdx.y;
    const int cbase = blockIdx.z * BN;

    const int ty = tid >> 4;   // 0..15 -> 8 batch rows each
    const int tx = tid & 15;   // 0..15 -> 8 output cols each

    int ce0 = d_cell[r * 3 + 0];
    int ce1 = d_cell[r * 3 + 1];
    int ce2 = d_cell[r * 3 + 2];

    // --- X tile loading: 128 rows x 16 gathered cols per chunk ---
    const int xrow = tid >> 2;            // 0..63 (two passes of 64 rows)
    const int xq   = (tid & 3) * 4;       // col quad within 16-wide chunk
    const float* xbase = x + (size_t)(m0 + xrow) * XCOLS + xq;

    // --- V tile loading: 16 k-rows x 128 cols per chunk ---
    const int vrow = tid >> 5;            // 0..7 (two passes of 8 rows)
    const int vq   = (tid & 31) * 4;
    const float* vbase = v + (size_t)r * CH + cbase + vq;  // + k*49*256

    float4 xr0, xr1, vr0, vr1;

    auto loadX = [&](int kc) {
        int e   = kc >> 2;
        int col = (e == 0 ? ce0 : (e == 1 ? ce1 : ce2)) * 64 + (kc & 3) * 16;
        const float* p = xbase + col;
        xr0 = *(const float4*)p;
        xr1 = *(const float4*)(p + (size_t)64 * XCOLS);
    };
    auto loadV = [&](int kc) {
        const float* p = vbase + (size_t)(kc * 16 + vrow) * (ROWS * CH);
        vr0 = *(const float4*)p;
        vr1 = *(const float4*)(p + (size_t)8 * ROWS * CH);
    };
    auto storeX = [&](int buf) {
        float* s = sX[buf];
        s[(xq + 0) * XS + xrow]      = xr0.x;
        s[(xq + 1) * XS + xrow]      = xr0.y;
        s[(xq + 2) * XS + xrow]      = xr0.z;
        s[(xq + 3) * XS + xrow]      = xr0.w;
        s[(xq + 0) * XS + xrow + 64] = xr1.x;
        s[(xq + 1) * XS + xrow + 64] = xr1.y;
        s[(xq + 2) * XS + xrow + 64] = xr1.z;
        s[(xq + 3) * XS + xrow + 64] = xr1.w;
    };
    auto storeV = [&](int buf) {
        *(float4*)&sV[buf][vrow * BN + vq]       = vr0;
        *(float4*)&sV[buf][(vrow + 8) * BN + vq] = vr1;
    };

    float2 acc[8][4];
#pragma unroll
    for (int i = 0; i < 8; i++)
#pragma unroll
        for (int j = 0; j < 4; j++) acc[i][j] = make_float2(0.f, 0.f);

    auto compute = [&](int buf) {
        const float* sx = sX[buf];
        const float* sv = sV[buf];
#pragma unroll
        for (int kk = 0; kk < KC; kk++) {
            float4 a0 = *(const float4*)&sx[kk * XS + ty * 8];
            float4 a1 = *(const float4*)&sx[kk * XS + ty * 8 + 4];
            float4 b0 = *(const float4*)&sv[kk * BN + tx * 8];
            float4 b1 = *(const float4*)&sv[kk * BN + tx * 8 + 4];
            float2 bp[4] = { make_float2(b0.x, b0.y), make_float2(b0.z, b0.w),
                             make_float2(b1.x, b1.y), make_float2(b1.z, b1.w) };
            float av[8] = { a0.x, a0.y, a0.z, a0.w, a1.x, a1.y, a1.z, a1.w };
#pragma unroll
            for (int i = 0; i < 8; i++) {
                float2 ap = make_float2(av[i], av[i]);
#pragma unroll
                for (int j = 0; j < 4; j++) ffma2(acc[i][j], ap, bp[j]);
            }
        }
    };

    // Prologue
    loadX(0); loadV(0);
    storeX(0); storeV(0);
    __syncthreads();

#pragma unroll 1
    for (int kc = 0; kc < NKC; kc++) {
        const int  cur  = kc & 1;
        const bool more = (kc + 1 < NKC);
        if (more) { loadX(kc + 1); loadV(kc + 1); }
        compute(cur);
        if (more) { storeX(cur ^ 1); storeV(cur ^ 1); __syncthreads(); }
    }

    // Epilogue: add bias, write out
    const float* bp_ = bias + (size_t)r * CH + cbase + tx * 8;
    float4 bs0 = *(const float4*)bp_;
    float4 bs1 = *(const float4*)(bp_ + 4);

#pragma unroll
    for (int i = 0; i < 8; i++) {
        size_t row = (size_t)(m0 + ty * 8 + i);
        float* po = out + row * OUTCOLS + (size_t)r * CH + cbase + tx * 8;
        float4 o0 = make_float4(acc[i][0].x + bs0.x, acc[i][0].y + bs0.y,
                                acc[i][1].x + bs0.z, acc[i][1].y + bs0.w);
        float4 o1 = make_float4(acc[i][2].x + bs1.x, acc[i][2].y + bs1.y,
                                acc[i][3].x + bs1.z, acc[i][3].y + bs1.w);
        *(float4*)po       = o0;
        *(float4*)(po + 4) = o1;
    }
}

extern "C" void kernel_launch(void* const* d_in, const int* in_sizes, int n_in,
                              void* d_out, int out_size) {
    (void)in_sizes; (void)n_in; (void)out_size;
    const float* x    = (const float*)d_in[0];
    const float* v    = (const float*)d_in[1];
    const float* bias = (const float*)d_in[2];
    float* out        = (float*)d_out;

    init_cells_kernel<<<1, 32>>>();
    dim3 grid(BATCH / BM, ROWS, CH / BN);
    ticrows_kernel<<<grid, 256>>>(x, v, bias, out);
}

// round 5
// speedup vs baseline: 2.8228x; 2.8228x over previous
#include <cuda_runtime.h>
#include <cuda_fp16.h>
#include <cstdint>
#include <cstddef>

// ---------------------------------------------------------------------------
// TicRows via mma.sync (m16n8k16 f16->f32). tcgen05 is unavailable: the harness
// compiles to compute_103 (no 'a'), which rejects arch-specific PTX features.
//
// out[n, r*256+c] = sum_{e,i} x[n, cell[r][e]*64+i] * v[e,i,r,c] + b[r*256+c]
// 49 GEMMs of (8192x192)@(192x256). CTA = 128 x 128 tile (col half), K chunks
// of 32, double-buffered smem in fp16, fp32 accumulate in registers.
// ---------------------------------------------------------------------------

#define BATCH   8192
#define ROWS    49
#define CH      256
#define XCOLS   1728
#define OUTCOLS 12544
#define BM      128
#define BN      128
#define NCHUNK  6
#define THREADS 256
#define SSTR    36          // smem row stride in halves (72B; conflict-free mma loads)

__device__ int d_cell[ROWS * 3];

__global__ void init_cells_kernel() {
    if (threadIdx.x != 0) return;
    int step = 0, col = 0;
    auto put = [&](int x, int y, int z) {
        d_cell[col * 3 + step] = x + 3 * y + 9 * z;
        step = (step + 1) % 3;
    };
    for (int x = 0; x < 3; x++) {
        for (int y = 0; y < 3; y++) { for (int z = 0; z < 3; z++) put(x, y, z); col++; }
        for (int z = 0; z < 3; z++) { for (int y = 0; y < 3; y++) put(x, y, z); col++; }
        for (int y = 0; y < 3; y++) put(x, y, y);       col++;
        for (int y = 0; y < 3; y++) put(x, y, 2 - y);   col++;
    }
    for (int z = 0; z < 3; z++) {
        for (int y = 0; y < 3; y++) { for (int x = 0; x < 3; x++) put(x, y, z); col++; }
        for (int y = 0; y < 3; y++) put(y, y, z);       col++;
        for (int y = 0; y < 3; y++) put(2 - y, y, z);   col++;
    }
    for (int y = 0; y < 3; y++) {
        for (int z = 0; z < 3; z++) put(z, y, z);       col++;
        for (int z = 0; z < 3; z++) put(2 - z, y, z);   col++;
    }
    for (int x = 0; x < 3; x++) put(x, x, x);           col++;
    for (int x = 0; x < 3; x++) put(x, 2 - x, 2 - x);   col++;
    for (int x = 0; x < 3; x++) put(x, x, 2 - x);       col++;
    for (int x = 0; x < 3; x++) put(x, 2 - x, x);       col++;
}

__device__ __forceinline__ uint32_t pack_half2(float a, float b) {
    __half2 h = __floats2half2_rn(a, b);
    return *reinterpret_cast<uint32_t*>(&h);
}

__device__ __forceinline__ void mma16816(float* c, uint32_t a0, uint32_t a1,
                                         uint32_t a2, uint32_t a3,
                                         uint32_t b0, uint32_t b1) {
    asm volatile(
        "mma.sync.aligned.m16n8k16.row.col.f32.f16.f16.f32 "
        "{%0,%1,%2,%3}, {%4,%5,%6,%7}, {%8,%9}, {%0,%1,%2,%3};"
        : "+f"(c[0]), "+f"(c[1]), "+f"(c[2]), "+f"(c[3])
        : "r"(a0), "r"(a1), "r"(a2), "r"(a3), "r"(b0), "r"(b1));
}

__global__ __launch_bounds__(THREADS, 2)
void ticrows_hmma(const float* __restrict__ x, const float* __restrict__ v,
                  const float* __restrict__ bias, float* __restrict__ out) {
    __shared__ __half sA[2][BM * SSTR];   // [m][k], k contiguous (32 + pad)
    __shared__ __half sB[2][BN * SSTR];   // [n][k]

    const int tid  = threadIdx.x;
    const int lane = tid & 31;
    const int wid  = tid >> 5;
    const int wm   = wid & 3;            // 4 warps along M  -> 32 rows each
    const int wn   = wid >> 2;           // 2 warps along N  -> 64 cols each
    const int m0   = blockIdx.x * BM;
    const int r    = blockIdx.y;
    const int nb0  = blockIdx.z * BN;    // 0 or 128 within the 256-wide row block

    const int ce0 = d_cell[r * 3 + 0];
    const int ce1 = d_cell[r * 3 + 1];
    const int ce2 = d_cell[r * 3 + 2];

    // ---- staging thread maps ----
    // A: 128 rows x 32 cols; 1024 float4-quads; 4 per thread.
    // B: 32 k x 128 n; n = tid&127 (coalesced), k = (tid>>7) + 2*i, 16 per thread.
    const int bn_ = tid & 127;
    const int bk_ = tid >> 7;
    const float* vb_base = v + (size_t)r * CH + nb0 + bn_;

    uint2  areg[4];          // packed fp16 quads for A
    __half breg[16];

    auto loadA = [&](int kc) {
        const int e       = kc >> 1;
        const int colbase = (e == 0 ? ce0 : (e == 1 ? ce1 : ce2)) * 64 + (kc & 1) * 32;
        const float* xb   = x + (size_t)m0 * XCOLS + colbase;
#pragma unroll
        for (int i = 0; i < 4; i++) {
            const int qi  = tid + i * 256;
            const int row = qi >> 3, q = qi & 7;
            float4 val = *(const float4*)(xb + (size_t)row * XCOLS + q * 4);
            areg[i].x = pack_half2(val.x, val.y);
            areg[i].y = pack_half2(val.z, val.w);
        }
    };
    auto loadB = [&](int kc) {
        const float* vb = vb_base + (size_t)kc * 32 * OUTCOLS;
#pragma unroll
        for (int i = 0; i < 16; i++)
            breg[i] = __float2half_rn(vb[(size_t)(bk_ + 2 * i) * OUTCOLS]);
    };
    auto storeA = [&](int buf) {
        __half* s = sA[buf];
#pragma unroll
        for (int i = 0; i < 4; i++) {
            const int qi  = tid + i * 256;
            const int row = qi >> 3, q = qi & 7;
            uint32_t* p = (uint32_t*)(s + row * SSTR + q * 4);
            p[0] = areg[i].x;
            p[1] = areg[i].y;
        }
    };
    auto storeB = [&](int buf) {
        __half* s = sB[buf] + bn_ * SSTR + bk_;
#pragma unroll
        for (int i = 0; i < 16; i++)
            s[2 * i] = breg[i];
    };

    float acc[2][8][4];
#pragma unroll
    for (int mb = 0; mb < 2; mb++)
#pragma unroll
        for (int nb = 0; nb < 8; nb++)
#pragma unroll
            for (int j = 0; j < 4; j++) acc[mb][nb][j] = 0.f;

    const int aq = 2 * (lane & 3);       // k offset within frag
    const int ag = lane >> 2;            // row/col group

    auto compute = [&](int buf) {
        const __half* sa = sA[buf];
        const __half* sb = sB[buf];
#pragma unroll
        for (int ks = 0; ks < 2; ks++) {
            const int k0 = ks * 16;
            uint32_t bf[8][2];
            const __half* pB = sb + (wn * 64 + ag) * SSTR + k0 + aq;
#pragma unroll
            for (int nb = 0; nb < 8; nb++) {
                bf[nb][0] = *(const uint32_t*)(pB + nb * 8 * SSTR);
                bf[nb][1] = *(const uint32_t*)(pB + nb * 8 * SSTR + 8);
            }
#pragma unroll
            for (int mb = 0; mb < 2; mb++) {
                const __half* pA = sa + (wm * 32 + mb * 16 + ag) * SSTR + k0 + aq;
                uint32_t a0 = *(const uint32_t*)pA;
                uint32_t a1 = *(const uint32_t*)(pA + 8 * SSTR);
                uint32_t a2 = *(const uint32_t*)(pA + 8);
                uint32_t a3 = *(const uint32_t*)(pA + 8 * SSTR + 8);
#pragma unroll
                for (int nb = 0; nb < 8; nb++)
                    mma16816(acc[mb][nb], a0, a1, a2, a3, bf[nb][0], bf[nb][1]);
            }
        }
    };

    // Prologue
    loadA(0); loadB(0);
    storeA(0); storeB(0);
    __syncthreads();

#pragma unroll 1
    for (int kc = 0; kc < NCHUNK; kc++) {
        const int  cur  = kc & 1;
        const bool more = (kc + 1 < NCHUNK);
        if (more) { loadA(kc + 1); loadB(kc + 1); }
        compute(cur);
        if (more) { storeA(cur ^ 1); storeB(cur ^ 1); __syncthreads(); }
    }

    // Epilogue: bias + store. Each (mb, nb, lane) owns rows g/g+8 and a col pair.
    const int colb = r * CH + nb0 + wn * 64 + aq;
#pragma unroll
    for (int nb = 0; nb < 8; nb++) {
        const float2 b2 = *(const float2*)(bias + colb + nb * 8);
#pragma unroll
        for (int mb = 0; mb < 2; mb++) {
            const int row0 = m0 + wm * 32 + mb * 16 + ag;
            float* p0 = out + (size_t)row0 * OUTCOLS + colb + nb * 8;
            float* p1 = p0 + (size_t)8 * OUTCOLS;
            *(float2*)p0 = make_float2(acc[mb][nb][0] + b2.x, acc[mb][nb][1] + b2.y);
            *(float2*)p1 = make_float2(acc[mb][nb][2] + b2.x, acc[mb][nb][3] + b2.y);
        }
    }
}

extern "C" void kernel_launch(void* const* d_in, const int* in_sizes, int n_in,
                              void* d_out, int out_size) {
    (void)in_sizes; (void)n_in; (void)out_size;
    const float* x    = (const float*)d_in[0];
    const float* v    = (const float*)d_in[1];
    const float* bias = (const float*)d_in[2];
    float* out        = (float*)d_out;

    init_cells_kernel<<<1, 32>>>();
    dim3 grid(BATCH / BM, ROWS, CH / BN);
    ticrows_hmma<<<grid, THREADS>>>(x, v, bias, out);
}

// round 6
// speedup vs baseline: 3.6337x; 1.2873x over previous
#include <cuda_runtime.h>
#include <cuda_fp16.h>
#include <cstdint>
#include <cstddef>

// ---------------------------------------------------------------------------
// TicRows via mma.sync m16n8k16 (fp16 in, fp32 acc), cp.async staging,
// ldmatrix fragment loads, conflict-free smem (stride 40 halves).
// Pre-pass converts x -> fp16 (g_xh, same layout) and v -> fp16 transposed
// k-contiguous (g_vT[r][n][k]); main GEMM then stages raw 16B chunks.
// out[n, r*256+c] = sum_{e,i} x[n, cell[r][e]*64+i]*v[e,i,r,c] + b[r*256+c]
// ---------------------------------------------------------------------------

#define BATCH   8192
#define ROWS    49
#define CH      256
#define XCOLS   1728
#define OUTCOLS 12544
#define KDIM    192
#define BM      128
#define BN      128
#define NCHUNK  6
#define THREADS 256
#define SSTR    40          // smem row stride in halves: 20 words -> all-bank map

__device__ int    d_cell[ROWS * 3];
__device__ __half g_xh[(size_t)BATCH * XCOLS];          // 28.3 MB
__device__ __half g_vT[(size_t)ROWS * CH * KDIM];       // 4.8 MB, [r][n][k]

__global__ void init_cells_kernel() {
    if (threadIdx.x != 0) return;
    int step = 0, col = 0;
    auto put = [&](int x, int y, int z) {
        d_cell[col * 3 + step] = x + 3 * y + 9 * z;
        step = (step + 1) % 3;
    };
    for (int x = 0; x < 3; x++) {
        for (int y = 0; y < 3; y++) { for (int z = 0; z < 3; z++) put(x, y, z); col++; }
        for (int z = 0; z < 3; z++) { for (int y = 0; y < 3; y++) put(x, y, z); col++; }
        for (int y = 0; y < 3; y++) put(x, y, y);       col++;
        for (int y = 0; y < 3; y++) put(x, y, 2 - y);   col++;
    }
    for (int z = 0; z < 3; z++) {
        for (int y = 0; y < 3; y++) { for (int x = 0; x < 3; x++) put(x, y, z); col++; }
        for (int y = 0; y < 3; y++) put(y, y, z);       col++;
        for (int y = 0; y < 3; y++) put(2 - y, y, z);   col++;
    }
    for (int y = 0; y < 3; y++) {
        for (int z = 0; z < 3; z++) put(z, y, z);       col++;
        for (int z = 0; z < 3; z++) put(2 - z, y, z);   col++;
    }
    for (int x = 0; x < 3; x++) put(x, x, x);           col++;
    for (int x = 0; x < 3; x++) put(x, 2 - x, 2 - x);   col++;
    for (int x = 0; x < 3; x++) put(x, x, 2 - x);       col++;
    for (int x = 0; x < 3; x++) put(x, 2 - x, x);       col++;
}

// x -> fp16, same layout. 8 elements per thread.
__global__ void convert_x_kernel(const float* __restrict__ x) {
    const size_t i8 = ((size_t)blockIdx.x * blockDim.x + threadIdx.x) * 8;
    float4 a = *(const float4*)(x + i8);
    float4 b = *(const float4*)(x + i8 + 4);
    __half2 h[4] = { __floats2half2_rn(a.x, a.y), __floats2half2_rn(a.z, a.w),
                     __floats2half2_rn(b.x, b.y), __floats2half2_rn(b.z, b.w) };
    *(uint4*)(g_xh + i8) = *(uint4*)h;
}

// v[(k)*49*256 + r*256 + n] -> g_vT[(r*256+n)*192 + k], fp16. One block per r.
__global__ void convert_v_kernel(const float* __restrict__ v) {
    const int r = blockIdx.x, n = threadIdx.x;
    const float* src = v + (size_t)r * CH + n;
    __half* dst = g_vT + ((size_t)r * CH + n) * KDIM;
#pragma unroll 1
    for (int kg = 0; kg < KDIM / 8; kg++) {
        __half2 h[4];
#pragma unroll
        for (int j = 0; j < 4; j++) {
            float f0 = src[(size_t)(kg * 8 + 2 * j)     * OUTCOLS];
            float f1 = src[(size_t)(kg * 8 + 2 * j + 1) * OUTCOLS];
            h[j] = __floats2half2_rn(f0, f1);
        }
        *(uint4*)(dst + kg * 8) = *(uint4*)h;
    }
}

// ------------------------------ PTX helpers -------------------------------

__device__ __forceinline__ uint32_t smem_u32(const void* p) {
    uint32_t a;
    asm("{ .reg .u64 t; cvta.to.shared.u64 t, %1; cvt.u32.u64 %0, t; }"
        : "=r"(a) : "l"(p));
    return a;
}

__device__ __forceinline__ void cp16(uint32_t dst, const void* src) {
    asm volatile("cp.async.ca.shared.global [%0], [%1], 16;"
                 :: "r"(dst), "l"(src) : "memory");
}
#define CP_COMMIT()  asm volatile("cp.async.commit_group;" ::: "memory")
#define CP_WAIT(n)   asm volatile("cp.async.wait_group %0;" :: "n"(n) : "memory")

__device__ __forceinline__ void ldmx4(uint32_t* r, uint32_t addr) {
    asm volatile("ldmatrix.sync.aligned.m8n8.x4.shared.b16 {%0,%1,%2,%3}, [%4];"
                 : "=r"(r[0]), "=r"(r[1]), "=r"(r[2]), "=r"(r[3]) : "r"(addr));
}

__device__ __forceinline__ void mma16816(float* c, uint32_t a0, uint32_t a1,
                                         uint32_t a2, uint32_t a3,
                                         uint32_t b0, uint32_t b1) {
    asm volatile(
        "mma.sync.aligned.m16n8k16.row.col.f32.f16.f16.f32 "
        "{%0,%1,%2,%3}, {%4,%5,%6,%7}, {%8,%9}, {%0,%1,%2,%3};"
        : "+f"(c[0]), "+f"(c[1]), "+f"(c[2]), "+f"(c[3])
        : "r"(a0), "r"(a1), "r"(a2), "r"(a3), "r"(b0), "r"(b1));
}

// ------------------------------- main kernel ------------------------------

__global__ __launch_bounds__(THREADS, 2)
void ticrows_hmma(const float* __restrict__ bias, float* __restrict__ out) {
    __shared__ __half sA[2][BM * SSTR];
    __shared__ __half sB[2][BN * SSTR];

    const int tid  = threadIdx.x;
    const int lane = tid & 31;
    const int wid  = tid >> 5;
    const int wm   = wid & 3;            // 4 warps along M -> 32 rows
    const int wn   = wid >> 2;           // 2 warps along N -> 64 cols
    const int m0   = blockIdx.x * BM;
    const int r    = blockIdx.y;
    const int nb0  = blockIdx.z * BN;

    const int ce0 = d_cell[r * 3 + 0];
    const int ce1 = d_cell[r * 3 + 1];
    const int ce2 = d_cell[r * 3 + 2];

    // staging maps: 512 16B-chunks per tile, 2 per thread for A and B each.
    // chunk c: row = c>>2, seg = c&3 (16B = 8 halves)
    const uint32_t sa_base = smem_u32(sA);
    const uint32_t sb_base = smem_u32(sB);

    auto stage = [&](int kc, int buf) {
        const int e       = kc >> 1;
        const int colbase = (e == 0 ? ce0 : (e == 1 ? ce1 : ce2)) * 64 + (kc & 1) * 32;
        const __half* xb  = g_xh + (size_t)m0 * XCOLS + colbase;
        const __half* vb  = g_vT + ((size_t)r * CH + nb0) * KDIM + kc * 32;
        const uint32_t da = sa_base + buf * (BM * SSTR * 2);
        const uint32_t db = sb_base + buf * (BN * SSTR * 2);
#pragma unroll
        for (int i = 0; i < 2; i++) {
            const int c   = tid + i * 256;
            const int row = c >> 2, seg = c & 3;
            cp16(da + (row * SSTR + seg * 8) * 2, xb + (size_t)row * XCOLS + seg * 8);
            cp16(db + (row * SSTR + seg * 8) * 2, vb + (size_t)row * KDIM  + seg * 8);
        }
    };

    float acc[2][8][4];
#pragma unroll
    for (int mb = 0; mb < 2; mb++)
#pragma unroll
        for (int nb = 0; nb < 8; nb++)
#pragma unroll
            for (int j = 0; j < 4; j++) acc[mb][nb][j] = 0.f;

    // ldmatrix lane addressing
    const int part = lane >> 3, l7 = lane & 7;
    // A: row = wm*32 + mb*16 + (part&1)*8 + l7 ; col = k0 + (part>>1)*8
    const int arow = wm * 32 + (part & 1) * 8 + l7;
    const int acol = (part >> 1) * 8;
    // B: n = wn*64 + nbp*16 + (part>>1)*8 + l7 ; col = k0 + (part&1)*8
    const int brow = wn * 64 + (part >> 1) * 8 + l7;
    const int bcol = (part & 1) * 8;

    auto compute = [&](int buf) {
        const uint32_t da = sa_base + buf * (BM * SSTR * 2);
        const uint32_t db = sb_base + buf * (BN * SSTR * 2);
#pragma unroll
        for (int ks = 0; ks < 2; ks++) {
            const int k0 = ks * 16;
            uint32_t af[2][4];
#pragma unroll
            for (int mb = 0; mb < 2; mb++)
                ldmx4(af[mb], da + ((arow + mb * 16) * SSTR + k0 + acol) * 2);
#pragma unroll
            for (int nbp = 0; nbp < 4; nbp++) {
                uint32_t bf[4];
                ldmx4(bf, db + ((brow + nbp * 16) * SSTR + k0 + bcol) * 2);
#pragma unroll
                for (int mb = 0; mb < 2; mb++) {
                    mma16816(acc[mb][2 * nbp],     af[mb][0], af[mb][1], af[mb][2],
                             af[mb][3], bf[0], bf[1]);
                    mma16816(acc[mb][2 * nbp + 1], af[mb][0], af[mb][1], af[mb][2],
                             af[mb][3], bf[2], bf[3]);
                }
            }
        }
    };

    // Pipeline: double-buffered cp.async
    stage(0, 0); CP_COMMIT();
#pragma unroll 1
    for (int kc = 0; kc < NCHUNK; kc++) {
        if (kc + 1 < NCHUNK) {
            stage(kc + 1, (kc + 1) & 1); CP_COMMIT();
            CP_WAIT(1);
        } else {
            CP_WAIT(0);
        }
        __syncthreads();
        compute(kc & 1);
        __syncthreads();
    }

    // Epilogue
    const int aq   = 2 * (lane & 3);
    const int ag   = lane >> 2;
    const int colb = r * CH + nb0 + wn * 64 + aq;
#pragma unroll
    for (int nb = 0; nb < 8; nb++) {
        const float2 b2 = *(const float2*)(bias + colb + nb * 8);
#pragma unroll
        for (int mb = 0; mb < 2; mb++) {
            const int row0 = m0 + wm * 32 + mb * 16 + ag;
            float* p0 = out + (size_t)row0 * OUTCOLS + colb + nb * 8;
            float* p1 = p0 + (size_t)8 * OUTCOLS;
            *(float2*)p0 = make_float2(acc[mb][nb][0] + b2.x, acc[mb][nb][1] + b2.y);
            *(float2*)p1 = make_float2(acc[mb][nb][2] + b2.x, acc[mb][nb][3] + b2.y);
        }
    }
}

extern "C" void kernel_launch(void* const* d_in, const int* in_sizes, int n_in,
                              void* d_out, int out_size) {
    (void)in_sizes; (void)n_in; (void)out_size;
    const float* x    = (const float*)d_in[0];
    const float* v    = (const float*)d_in[1];
    const float* bias = (const float*)d_in[2];
    float* out        = (float*)d_out;

    init_cells_kernel<<<1, 32>>>();
    convert_x_kernel<<<(BATCH * XCOLS) / (256 * 8), 256>>>(x);
    convert_v_kernel<<<ROWS, CH>>>(v);
    dim3 grid(BATCH / BM, ROWS, CH / BN);
    ticrows_hmma<<<grid, THREADS>>>(bias, out);
}